// round 1
// baseline (speedup 1.0000x reference)
#include <cuda_runtime.h>
#include <math.h>
#include <stdint.h>
#include <stddef.h>

#define B_ 128
#define H_ 8
#define DK 64
#define C_ 50000
#define D_ 512
#define TILE_C 128
#define NTILE ((C_ + TILE_C - 1) / TILE_C)   // 391

// margin constants (double-precision evaluated, stored as float)
#define COS_M 0.9800665778412416f
#define SIN_M 0.19866933079506122f
#define TH_  (-0.9800665778412416f)          // cos(pi - m) = -cos(m)
#define MM_  0.039733866159012244f           // sin(pi - m)*m = sin(m)*m
#define S_   30.0f

// ---------------- scratch (device globals; no runtime allocation) ----------
__device__ float g_E[(size_t)B_ * H_ * C_];          // exp(logit - 30), [b][h][c]  (204.8 MB)
__device__ float g_xn[B_ * H_ * DK];                 // normalized x, [b][h][k]
__device__ float g_winv[H_ * C_];                    // 1/max(||w_col||, eps)
__device__ float g_psum[H_ * NTILE * B_];            // per-tile partial sums of exp
__device__ float g_sumexp[H_ * B_];                  // [h*128 + b]
__device__ float g_invsum[B_ * H_];                  // [b*8 + h]
__device__ int   g_label[B_];

// ---------------- label decode (int32 vs int64 auto-detect) ----------------
__global__ void k_label(const int* __restrict__ raw) {
    __shared__ int is64;
    if (threadIdx.x == 0) {
        // If stored as int64 little-endian, words [1,3,5,...] are the high
        // halves of labels < 50000 -> all zero. Only first 512 bytes are
        // inspected, which exist in both layouts.
        int all0 = 1;
        for (int i = 0; i < 64; i++) {
            if (raw[2 * i + 1] != 0) { all0 = 0; break; }
        }
        is64 = all0;
    }
    __syncthreads();
    int t = threadIdx.x;
    if (t < B_) g_label[t] = is64 ? raw[2 * t] : raw[t];
}

// ---------------- x normalization ------------------------------------------
__global__ void k_xnorm(const float* __restrict__ x) {
    int b = blockIdx.x;
    int t = threadIdx.x;                 // 0..511
    float v = x[b * D_ + t];
    float s = v * v;
    #pragma unroll
    for (int o = 16; o > 0; o >>= 1) s += __shfl_down_sync(0xffffffffu, s, o);
    __shared__ float wp[16];
    int w = t >> 5, lane = t & 31;
    if (lane == 0) wp[w] = s;
    __syncthreads();
    int h = t >> 6;
    float ss = wp[2 * h] + wp[2 * h + 1];
    float inv = 1.0f / fmaxf(sqrtf(ss), 1e-12f);
    g_xn[b * D_ + t] = v * inv;          // (b*8+h)*64+k == b*512+t
}

// ---------------- weight column inverse norms ------------------------------
__global__ void k_winv(const float* __restrict__ w) {
    int idx = blockIdx.x * blockDim.x + threadIdx.x;
    if (idx >= H_ * C_) return;
    int h = idx / C_, c = idx - h * C_;
    const float* p = w + (size_t)h * DK * C_ + c;
    float ss = 0.f;
    #pragma unroll
    for (int k = 0; k < DK; k++) { float v = p[(size_t)k * C_]; ss += v * v; }
    g_winv[idx] = 1.0f / fmaxf(sqrtf(ss), 1e-12f);
}

// ---------------- main fused GEMM + AAM + exp + partial softmax sums --------
// grid (NTILE, H), 256 threads, dynamic smem
__global__ __launch_bounds__(256) void k_gemm(const float* __restrict__ w) {
    extern __shared__ float smem[];
    float* As = smem;                         // [64][129]
    float* Ws = As + DK * 129;                // [64][132]
    float* ps = Ws + DK * 132;                // [128][16]

    const int tid = threadIdx.x;
    const int h = blockIdx.y;
    const int c0 = blockIdx.x * TILE_C;

    // load A tile: As[k][b] = xn[b][h][k]
    for (int idx = tid; idx < B_ * DK; idx += 256) {
        int b = idx >> 6, k = idx & 63;
        As[k * 129 + b] = g_xn[b * D_ + h * DK + k];
    }
    // load W tile: Ws[k][cc] = w[h][k][c0+cc]  (zero pad at the tail)
    for (int idx = tid; idx < DK * TILE_C; idx += 256) {
        int k = idx >> 7, cc = idx & 127;
        int c = c0 + cc;
        Ws[k * 132 + cc] = (c < C_) ? w[((size_t)h * DK + k) * C_ + c] : 0.f;
    }
    __syncthreads();

    const int ty = tid >> 4;    // b-group (16 groups * 8 rows)
    const int tx = tid & 15;    // c-group (16 groups * 8 cols)

    float acc[8][8];
    #pragma unroll
    for (int i = 0; i < 8; i++)
        #pragma unroll
        for (int j = 0; j < 8; j++) acc[i][j] = 0.f;

    #pragma unroll 8
    for (int k = 0; k < DK; k++) {
        float a[8];
        #pragma unroll
        for (int i = 0; i < 8; i++) a[i] = As[k * 129 + ty * 8 + i];
        float4 w0 = *(const float4*)&Ws[k * 132 + tx * 8];
        float4 w1 = *(const float4*)&Ws[k * 132 + tx * 8 + 4];
        float wv[8] = {w0.x, w0.y, w0.z, w0.w, w1.x, w1.y, w1.z, w1.w};
        #pragma unroll
        for (int i = 0; i < 8; i++)
            #pragma unroll
            for (int j = 0; j < 8; j++)
                acc[i][j] = fmaf(a[i], wv[j], acc[i][j]);
    }

    // epilogue: cosine -> AAM margin at label -> exp(logit-30)
    float winvv[8];
    #pragma unroll
    for (int j = 0; j < 8; j++) {
        int c = c0 + tx * 8 + j;
        winvv[j] = (c < C_) ? g_winv[h * C_ + c] : 0.f;
    }

    const bool full = (c0 + TILE_C <= C_);
    #pragma unroll
    for (int i = 0; i < 8; i++) {
        int b = ty * 8 + i;
        int lb = g_label[b];
        float ev[8];
        float bsum = 0.f;
        #pragma unroll
        for (int j = 0; j < 8; j++) {
            int c = c0 + tx * 8 + j;
            float cos = acc[i][j] * winvv[j];
            float val = cos;
            if (c == lb) {
                float sine = sqrtf(fmaxf(1.0f - cos * cos, 0.0f));
                float phi = cos * COS_M - sine * SIN_M;
                val = (cos - TH_ > 0.0f) ? phi : (cos - MM_);
            }
            float e = (c < C_) ? __expf(S_ * val - S_) : 0.f;
            ev[j] = e;
            bsum += e;
        }
        size_t off = ((size_t)b * H_ + h) * C_ + c0 + tx * 8;
        if (full) {
            *(float4*)&g_E[off]     = make_float4(ev[0], ev[1], ev[2], ev[3]);
            *(float4*)&g_E[off + 4] = make_float4(ev[4], ev[5], ev[6], ev[7]);
        } else {
            #pragma unroll
            for (int j = 0; j < 8; j++)
                if (c0 + tx * 8 + j < C_) g_E[off + j] = ev[j];
        }
        ps[b * 16 + tx] = bsum;    // overwritten per-i? no: unique (b,tx) per thread-i pair
    }
    __syncthreads();
    // deterministic per-b reduce over the 16 tx partials
    if (tid < B_) {
        float s = 0.f;
        #pragma unroll
        for (int t = 0; t < 16; t++) s += ps[tid * 16 + t];
        g_psum[((size_t)h * NTILE + blockIdx.x) * B_ + tid] = s;
    }
}

// ---------------- reduce partial sums -> sumexp, invsum ---------------------
__global__ void k_sumexp() {
    int g = blockIdx.x * blockDim.x + threadIdx.x;   // h*128 + b
    if (g >= H_ * B_) return;
    int h = g >> 7, b = g & 127;
    float s = 0.f;
    for (int t = 0; t < NTILE; t++) s += g_psum[((size_t)h * NTILE + t) * B_ + b];
    g_sumexp[g] = s;
    g_invsum[b * H_ + h] = 1.0f / s;
}

// ---------------- loss: label logit + log-sum-exp, mean over 1024 ----------
__global__ void k_loss(const float* __restrict__ w, float* __restrict__ out,
                       int write_loss) {
    int tid = threadIdx.x;                 // 0..1023
    int b = tid >> 3, h = tid & 7;
    int lb = g_label[b];
    const float* wp = w + (size_t)h * DK * C_ + lb;
    float dot = 0.f;
    #pragma unroll
    for (int k = 0; k < DK; k++)
        dot = fmaf(g_xn[b * D_ + h * DK + k], wp[(size_t)k * C_], dot);
    float cos = dot * g_winv[h * C_ + lb];
    float sine = sqrtf(fmaxf(1.0f - cos * cos, 0.0f));
    float phi = cos * COS_M - sine * SIN_M;
    float val = (cos - TH_ > 0.0f) ? phi : (cos - MM_);
    float logit = S_ * val;
    float nll = -(logit - S_ - logf(g_sumexp[h * 128 + b]));

    __shared__ float red[1024];
    red[tid] = nll;
    __syncthreads();
    #pragma unroll
    for (int s = 512; s > 0; s >>= 1) {
        if (tid < s) red[tid] += red[tid + s];
        __syncthreads();
    }
    if (tid == 0 && write_loss)
        out[(size_t)B_ * C_] = red[0] * (1.0f / (B_ * H_));
}

// ---------------- output: mean over heads of softmax ------------------------
__global__ void k_out(float* __restrict__ out) {
    int g = blockIdx.x * blockDim.x + threadIdx.x;   // over B_*C_/4
    if (g >= B_ * (C_ / 4)) return;
    int b = g / (C_ / 4);
    int c4 = (g - b * (C_ / 4)) * 4;
    float4 o = make_float4(0.f, 0.f, 0.f, 0.f);
    #pragma unroll
    for (int h = 0; h < H_; h++) {
        float inv = g_invsum[b * H_ + h];
        float4 e = *(const float4*)&g_E[((size_t)b * H_ + h) * C_ + c4];
        o.x = fmaf(e.x, inv, o.x);
        o.y = fmaf(e.y, inv, o.y);
        o.z = fmaf(e.z, inv, o.z);
        o.w = fmaf(e.w, inv, o.w);
    }
    o.x *= 0.125f; o.y *= 0.125f; o.z *= 0.125f; o.w *= 0.125f;
    *(float4*)&out[(size_t)b * C_ + c4] = o;
}

// ---------------- launcher ---------------------------------------------------
extern "C" void kernel_launch(void* const* d_in, const int* in_sizes, int n_in,
                              void* d_out, int out_size) {
    const float* x = (const float*)d_in[0];
    const float* w = (const float*)d_in[1];
    const int*   lab = (const int*)d_in[2];
    float* out = (float*)d_out;
    (void)in_sizes; (void)n_in;

    static int smem_set = 0;
    const int GEMM_SMEM = (DK * 129 + DK * 132 + B_ * 16) * (int)sizeof(float);
    if (!smem_set) {
        cudaFuncSetAttribute(k_gemm, cudaFuncAttributeMaxDynamicSharedMemorySize,
                             GEMM_SMEM);
        smem_set = 1;
    }

    int write_loss = (out_size > B_ * C_) ? 1 : 0;

    k_label<<<1, 128>>>(lab);
    k_xnorm<<<B_, D_>>>(x);
    k_winv<<<(H_ * C_ + 255) / 256, 256>>>(w);
    {
        dim3 grid(NTILE, H_);
        k_gemm<<<grid, 256, GEMM_SMEM>>>(w);
    }
    k_sumexp<<<(H_ * B_ + 255) / 256, 256>>>();
    k_loss<<<1, 1024>>>(w, out, write_loss);
    k_out<<<(B_ * (C_ / 4) + 255) / 256, 256>>>(out);
}

// round 3
// speedup vs baseline: 2.2286x; 2.2286x over previous
#include <cuda_runtime.h>
#include <cuda_bf16.h>
#include <math.h>
#include <stdint.h>
#include <stddef.h>

#define B_ 128
#define H_ 8
#define DK 64
#define C_ 50000
#define D_ 512
#define TILE_C 128
#define NTILE 391

#define COS_M 0.9800665778412416f
#define SIN_M 0.19866933079506122f
#define TH_  (-0.9800665778412416f)
#define MM_  0.039733866159012244f
#define S_   30.0f

// ---- pass1 smem layout (bytes) ----
#define OFF_AH 0
#define OFF_AL 16384
#define OFF_BH 32768
#define OFF_BL 49152
#define OFF_WINV 65536
#define OFF_WP   66048
#define OFF_PS   67072
#define SMEM1    68096

// ---- k_out smem ----
#define KO_INV 0
#define KO_STG 4096
#define SMEM2 (4096 + 128 * 130 * 4)   // 70656

// ---------------- device scratch ----------------
__device__ __align__(16) __nv_bfloat16 g_Asw[H_ * 16384];  // per head: [hi 8192][lo 8192], swizzled
__device__ float g_E[(size_t)H_ * NTILE * 8 * 2048];       // frag-layout exp values (205MB)
__device__ float g_psum[H_ * NTILE * B_];
__device__ float g_sumexp[H_ * B_];
__device__ float g_invsum[B_ * H_];
__device__ float g_coslab[B_ * H_];
__device__ int   g_label[B_];

// ---------------- helpers ----------------
__device__ __forceinline__ uint32_t smem_u32(const void* p) {
    uint32_t a;
    asm("{ .reg .u64 t; cvta.to.shared.u64 t, %1; cvt.u32.u64 %0, t; }" : "=r"(a) : "l"(p));
    return a;
}
__device__ __forceinline__ unsigned swz(unsigned by) { return by ^ ((by >> 3) & 0x70); }

__device__ __forceinline__ void ldsm4(uint32_t* r, uint32_t addr) {
    asm volatile("ldmatrix.sync.aligned.m8n8.x4.shared.b16 {%0,%1,%2,%3}, [%4];"
                 : "=r"(r[0]), "=r"(r[1]), "=r"(r[2]), "=r"(r[3]) : "r"(addr));
}
__device__ __forceinline__ void mma_bf16(float* d, const uint32_t* a, uint32_t b0, uint32_t b1) {
    asm volatile("mma.sync.aligned.m16n8k16.row.col.f32.bf16.bf16.f32 "
                 "{%0,%1,%2,%3}, {%4,%5,%6,%7}, {%8,%9}, {%0,%1,%2,%3};"
                 : "+f"(d[0]), "+f"(d[1]), "+f"(d[2]), "+f"(d[3])
                 : "r"(a[0]), "r"(a[1]), "r"(a[2]), "r"(a[3]), "r"(b0), "r"(b1));
}
__device__ __forceinline__ uint32_t packbf(__nv_bfloat16 a, __nv_bfloat16 b) {
    return (uint32_t)__bfloat16_as_ushort(a) | ((uint32_t)__bfloat16_as_ushort(b) << 16);
}

// ---------------- small kernels ----------------
__global__ void k_label(const int* __restrict__ raw) {
    __shared__ int is64;
    if (threadIdx.x == 0) {
        int all0 = 1;
        for (int i = 0; i < 64; i++) if (raw[2 * i + 1] != 0) { all0 = 0; break; }
        is64 = all0;
    }
    __syncthreads();
    int t = threadIdx.x;
    if (t < B_) g_label[t] = is64 ? raw[2 * t] : raw[t];
}

__global__ void k_xnorm(const float* __restrict__ x) {
    int b = blockIdx.x, t = threadIdx.x;
    float v = x[b * D_ + t];
    float s = v * v;
    #pragma unroll
    for (int o = 16; o > 0; o >>= 1) s += __shfl_down_sync(0xffffffffu, s, o);
    __shared__ float wpz[16];
    if ((t & 31) == 0) wpz[t >> 5] = s;
    __syncthreads();
    int h = t >> 6, k = t & 63;
    float ss = wpz[2 * h] + wpz[2 * h + 1];
    float xn = v * (1.0f / fmaxf(sqrtf(ss), 1e-12f));
    __nv_bfloat16 hi = __float2bfloat16(xn);
    __nv_bfloat16 lo = __float2bfloat16(xn - __bfloat162float(hi));
    unsigned by = (unsigned)b * 128u + 2u * (unsigned)k;
    unsigned sw = swz(by);
    g_Asw[h * 16384 + (sw >> 1)] = hi;
    g_Asw[h * 16384 + 8192 + (sw >> 1)] = lo;
}

// ---------------- pass1: GEMM + margin + exp + partial sums ----------------
__global__ __launch_bounds__(256, 2) void k_pass1(const float* __restrict__ w) {
    extern __shared__ char sm[];
    const int tid = threadIdx.x, warp = tid >> 5, lane = tid & 31;
    const int h = blockIdx.y, tile = blockIdx.x, c0 = tile * TILE_C;
    uint32_t sb = smem_u32(sm);

    // copy A limbs (32KB, pre-swizzled)
    {
        const uint4* src = (const uint4*)(g_Asw + h * 16384);
        uint4* dst = (uint4*)(sm + OFF_AH);
        #pragma unroll
        for (int i = 0; i < 8; i++) dst[tid + 256 * i] = src[tid + 256 * i];
    }
    // convert B tile to bf16 limbs (+ per-column sq-norm partial)
    {
        int c = tid & 127, halfk = tid >> 7;
        int cg = c0 + c;
        bool valid = cg < C_;
        const float* wp0 = w + ((size_t)(h * DK + halfk * 32)) * C_ + cg;
        float ss = 0.f;
        #pragma unroll
        for (int i = 0; i < 16; i++) {
            float v0 = valid ? __ldg(wp0 + (size_t)(2 * i) * C_) : 0.f;
            float v1 = valid ? __ldg(wp0 + (size_t)(2 * i + 1) * C_) : 0.f;
            ss = fmaf(v0, v0, ss); ss = fmaf(v1, v1, ss);
            __nv_bfloat16 h0 = __float2bfloat16(v0);
            __nv_bfloat16 h1 = __float2bfloat16(v1);
            __nv_bfloat16 l0 = __float2bfloat16(v0 - __bfloat162float(h0));
            __nv_bfloat16 l1 = __float2bfloat16(v1 - __bfloat162float(h1));
            unsigned by = (unsigned)c * 128u + (unsigned)(halfk * 64 + 4 * i);
            unsigned sw = swz(by);
            *(uint32_t*)(sm + OFF_BH + sw) = packbf(h0, h1);
            *(uint32_t*)(sm + OFF_BL + sw) = packbf(l0, l1);
        }
        ((float*)(sm + OFF_WP))[c * 2 + halfk] = ss;
    }
    __syncthreads();
    if (tid < 128) {
        float* wp = (float*)(sm + OFF_WP);
        ((float*)(sm + OFF_WINV))[tid] =
            1.0f / fmaxf(sqrtf(wp[tid * 2] + wp[tid * 2 + 1]), 1e-12f);
    }

    const int wm = warp >> 1, wn = warp & 1;
    const int m0 = wm * 32, n0 = wn * 64;
    const int lrow = lane & 7, lt = lane >> 3;
    const int rowAo = lrow + (lt & 1) * 8;
    const int kbAo = (lt >> 1) * 16;
    const int rowBo = lrow + (lt >> 1) * 8;
    const int kbBo = (lt & 1) * 16;

    float acc[64];
    #pragma unroll
    for (int i = 0; i < 64; i++) acc[i] = 0.f;

    #pragma unroll
    for (int ks = 0; ks < 4; ks++) {
        uint32_t aH[2][4], aL[2][4];
        #pragma unroll
        for (int mb = 0; mb < 2; mb++) {
            unsigned sw = swz((unsigned)((m0 + mb * 16 + rowAo) * 128 + ks * 32 + kbAo));
            ldsm4(aH[mb], sb + OFF_AH + sw);
            ldsm4(aL[mb], sb + OFF_AL + sw);
        }
        #pragma unroll
        for (int p = 0; p < 4; p++) {
            unsigned sw = swz((unsigned)((n0 + p * 16 + rowBo) * 128 + ks * 32 + kbBo));
            uint32_t bH[4], bL[4];
            ldsm4(bH, sb + OFF_BH + sw);
            ldsm4(bL, sb + OFF_BL + sw);
            #pragma unroll
            for (int mb = 0; mb < 2; mb++) {
                float* d0 = acc + (mb * 8 + p * 2) * 4;
                float* d1 = acc + (mb * 8 + p * 2 + 1) * 4;
                mma_bf16(d0, aH[mb], bH[0], bH[1]);
                mma_bf16(d1, aH[mb], bH[2], bH[3]);
                mma_bf16(d0, aH[mb], bL[0], bL[1]);
                mma_bf16(d1, aH[mb], bL[2], bL[3]);
                mma_bf16(d0, aL[mb], bH[0], bH[1]);
                mma_bf16(d1, aL[mb], bH[2], bH[3]);
                mma_bf16(d0, aL[mb], bL[0], bL[1]);
                mma_bf16(d1, aL[mb], bL[2], bL[3]);
            }
        }
    }
    __syncthreads();

    // epilogue in fragment registers
    const float* winv = (const float*)(sm + OFF_WINV);
    float* ps = (float*)(sm + OFF_PS);
    const int r0 = m0 + (lane >> 2);
    int labr[4];
    #pragma unroll
    for (int i = 0; i < 4; i++) labr[i] = g_label[r0 + (i >> 1) * 16 + (i & 1) * 8];

    float rsum[4] = {0.f, 0.f, 0.f, 0.f};
    const size_t wbase = (((size_t)h * NTILE + tile) * 8 + warp) * 2048;

    #pragma unroll
    for (int mb = 0; mb < 2; mb++) {
        #pragma unroll
        for (int pn = 0; pn < 8; pn++) {
            int cb = n0 + pn * 8 + (lane & 3) * 2;
            float w0 = winv[cb], w1 = winv[cb + 1];
            int cg = c0 + cb;
            #pragma unroll
            for (int pr = 0; pr < 2; pr++) {
                int row = r0 + mb * 16 + pr * 8;
                int lb = labr[mb * 2 + pr];
                float v0 = acc[(mb * 8 + pn) * 4 + pr * 2 + 0];
                float v1 = acc[(mb * 8 + pn) * 4 + pr * 2 + 1];
                float cos0 = v0 * w0, cos1 = v1 * w1;
                float e0 = 0.f, e1 = 0.f;
                if (cg < C_) {
                    float val = cos0;
                    if (cg == lb) {
                        float sn = sqrtf(fmaxf(1.f - cos0 * cos0, 0.f));
                        float ph = cos0 * COS_M - sn * SIN_M;
                        val = (cos0 > TH_) ? ph : (cos0 - MM_);
                        g_coslab[row * H_ + h] = cos0;
                    }
                    e0 = __expf(S_ * val - S_);
                }
                if (cg + 1 < C_) {
                    float val = cos1;
                    if (cg + 1 == lb) {
                        float sn = sqrtf(fmaxf(1.f - cos1 * cos1, 0.f));
                        float ph = cos1 * COS_M - sn * SIN_M;
                        val = (cos1 > TH_) ? ph : (cos1 - MM_);
                        g_coslab[row * H_ + h] = cos1;
                    }
                    e1 = __expf(S_ * val - S_);
                }
                rsum[mb * 2 + pr] += e0 + e1;
                *(float2*)&g_E[wbase + (size_t)(mb * 8 + pn) * 128 + pr * 64 + lane * 2] =
                    make_float2(e0, e1);
            }
        }
    }
    #pragma unroll
    for (int i = 0; i < 4; i++) {
        float v = rsum[i];
        v += __shfl_down_sync(0xffffffffu, v, 1);
        v += __shfl_down_sync(0xffffffffu, v, 2);
        if ((lane & 3) == 0)
            ps[(r0 + (i >> 1) * 16 + (i & 1) * 8) * 2 + wn] = v;
    }
    __syncthreads();
    if (tid < 128)
        g_psum[((size_t)h * NTILE + tile) * B_ + tid] = ps[tid * 2] + ps[tid * 2 + 1];
}

// ---------------- reductions / loss ----------------
__global__ void k_sumexp() {
    int h = blockIdx.x, b = threadIdx.x;
    float s = 0.f;
    for (int t = 0; t < NTILE; t++) s += g_psum[((size_t)h * NTILE + t) * B_ + b];
    g_sumexp[h * B_ + b] = s;
    g_invsum[b * H_ + h] = 1.0f / s;
}

__global__ void k_loss(float* __restrict__ out, int write_loss) {
    int tid = threadIdx.x;
    int b = tid >> 3, h = tid & 7;
    float cos = g_coslab[b * H_ + h];
    float sine = sqrtf(fmaxf(1.0f - cos * cos, 0.0f));
    float phi = cos * COS_M - sine * SIN_M;
    float val = (cos > TH_) ? phi : (cos - MM_);
    float nll = -(S_ * val - S_ - logf(g_sumexp[h * B_ + b]));
    __shared__ float red[1024];
    red[tid] = nll;
    __syncthreads();
    #pragma unroll
    for (int s = 512; s > 0; s >>= 1) {
        if (tid < s) red[tid] += red[tid + s];
        __syncthreads();
    }
    if (tid == 0 && write_loss) out[(size_t)B_ * C_] = red[0] * (1.0f / (B_ * H_));
}

// ---------------- k_out: head-mean of softmax ----------------
__global__ __launch_bounds__(256, 2) void k_out(float* __restrict__ out) {
    extern __shared__ char sm[];
    const int tid = threadIdx.x, warp = tid >> 5, lane = tid & 31;
    const int tile = blockIdx.x, c0 = tile * TILE_C;
    float* invs = (float*)(sm + KO_INV);
    float* stg = (float*)(sm + KO_STG);
    #pragma unroll
    for (int i = 0; i < 4; i++) invs[tid + 256 * i] = g_invsum[tid + 256 * i] * 0.125f;
    __syncthreads();

    const int wm = warp >> 1, wn = warp & 1;
    const int m0 = wm * 32, n0 = wn * 64;
    const int r0 = m0 + (lane >> 2);

    float acc[64];
    #pragma unroll
    for (int i = 0; i < 64; i++) acc[i] = 0.f;

    for (int h = 0; h < H_; h++) {
        const float* Ep = g_E + (((size_t)h * NTILE + tile) * 8 + warp) * 2048;
        float s[4];
        #pragma unroll
        for (int i = 0; i < 4; i++)
            s[i] = invs[(r0 + (i >> 1) * 16 + (i & 1) * 8) * H_ + h];
        #pragma unroll
        for (int mb = 0; mb < 2; mb++)
            #pragma unroll
            for (int pn = 0; pn < 8; pn++)
                #pragma unroll
                for (int pr = 0; pr < 2; pr++) {
                    float2 v = *(const float2*)&Ep[(size_t)(mb * 8 + pn) * 128 + pr * 64 + lane * 2];
                    float sv = s[mb * 2 + pr];
                    int ai = (mb * 8 + pn) * 4 + pr * 2;
                    acc[ai]     = fmaf(v.x, sv, acc[ai]);
                    acc[ai + 1] = fmaf(v.y, sv, acc[ai + 1]);
                }
    }
    #pragma unroll
    for (int mb = 0; mb < 2; mb++)
        #pragma unroll
        for (int pn = 0; pn < 8; pn++)
            #pragma unroll
            for (int pr = 0; pr < 2; pr++) {
                int row = r0 + mb * 16 + pr * 8;
                int col = n0 + pn * 8 + (lane & 3) * 2;
                int ai = (mb * 8 + pn) * 4 + pr * 2;
                stg[row * 130 + col] = acc[ai];
                stg[row * 130 + col + 1] = acc[ai + 1];
            }
    __syncthreads();
    for (int idx = tid; idx < 4096; idx += 256) {
        int b = idx >> 5, c4 = (idx & 31) << 2;
        int cg = c0 + c4;
        if (cg + 3 < C_) {
            float4 vv = make_float4(stg[b * 130 + c4], stg[b * 130 + c4 + 1],
                                    stg[b * 130 + c4 + 2], stg[b * 130 + c4 + 3]);
            *(float4*)&out[(size_t)b * C_ + cg] = vv;
        } else {
            #pragma unroll
            for (int j = 0; j < 4; j++)
                if (cg + j < C_) out[(size_t)b * C_ + cg + j] = stg[b * 130 + c4 + j];
        }
    }
}

// ---------------- launcher ----------------
extern "C" void kernel_launch(void* const* d_in, const int* in_sizes, int n_in,
                              void* d_out, int out_size) {
    const float* x = (const float*)d_in[0];
    const float* w = (const float*)d_in[1];
    const int*   lab = (const int*)d_in[2];
    float* out = (float*)d_out;
    (void)in_sizes; (void)n_in;

    static int inited = 0;
    if (!inited) {
        cudaFuncSetAttribute(k_pass1, cudaFuncAttributeMaxDynamicSharedMemorySize, SMEM1);
        cudaFuncSetAttribute(k_out, cudaFuncAttributeMaxDynamicSharedMemorySize, SMEM2);
        inited = 1;
    }
    int write_loss = (out_size > B_ * C_) ? 1 : 0;

    k_label<<<1, 128>>>(lab);
    k_xnorm<<<B_, D_>>>(x);
    {
        dim3 g1(NTILE, H_);
        k_pass1<<<g1, 256, SMEM1>>>(w);
    }
    k_sumexp<<<H_, B_>>>();
    k_loss<<<1, 1024>>>(out, write_loss);
    k_out<<<NTILE, 256, SMEM2>>>(out);
}

// round 4
// speedup vs baseline: 2.4404x; 1.0950x over previous
#include <cuda_runtime.h>
#include <cuda_bf16.h>
#include <math.h>
#include <stdint.h>
#include <stddef.h>

#define B_ 128
#define H_ 8
#define DK 64
#define C_ 50000
#define D_ 512
#define TILE_C 128
#define NTILE 391
#define NCHUNK 8
#define CHTILES 49   // 8*49 = 392 >= 391

#define COS_M 0.9800665778412416f
#define SIN_M 0.19866933079506122f
#define TH_  (-0.9800665778412416f)
#define MM_  0.039733866159012244f
#define S_   30.0f
#define QS   31500.0f
#define QINV (S_ / QS)

// ---- pass1 smem layout (bytes) ----
#define OFF_AH 0
#define OFF_AL 16384
#define OFF_BH 32768
#define OFF_BL 49152
#define OFF_WINV 65536
#define OFF_WP   66048
#define OFF_PS   67072
#define SMEM1    68096

// ---- k_out smem ----
#define KO_INV 0
#define KO_STG 4096
#define SMEM2 (4096 + 128 * 130 * 4)   // 70656

// ---------------- device scratch ----------------
__device__ __align__(16) __nv_bfloat16 g_Asw[H_ * 16384];   // per head: [hi][lo], swizzled
__device__ uint32_t g_Q[(size_t)H_ * NTILE * 8 * 1024];     // packed int16 q-pairs (102MB)
__device__ float g_psum[H_ * NTILE * B_];
__device__ float g_psum2[H_ * NCHUNK * B_];
__device__ float g_invsum[B_ * H_];
__device__ float g_coslab[B_ * H_];
__device__ int   g_label[B_];

// ---------------- helpers ----------------
__device__ __forceinline__ uint32_t smem_u32(const void* p) {
    uint32_t a;
    asm("{ .reg .u64 t; cvta.to.shared.u64 t, %1; cvt.u32.u64 %0, t; }" : "=r"(a) : "l"(p));
    return a;
}
__device__ __forceinline__ unsigned swz(unsigned by) { return by ^ ((by >> 3) & 0x70); }

__device__ __forceinline__ void ldsm4(uint32_t* r, uint32_t addr) {
    asm volatile("ldmatrix.sync.aligned.m8n8.x4.shared.b16 {%0,%1,%2,%3}, [%4];"
                 : "=r"(r[0]), "=r"(r[1]), "=r"(r[2]), "=r"(r[3]) : "r"(addr));
}
__device__ __forceinline__ void mma_bf16(float* d, const uint32_t* a, uint32_t b0, uint32_t b1) {
    asm volatile("mma.sync.aligned.m16n8k16.row.col.f32.bf16.bf16.f32 "
                 "{%0,%1,%2,%3}, {%4,%5,%6,%7}, {%8,%9}, {%0,%1,%2,%3};"
                 : "+f"(d[0]), "+f"(d[1]), "+f"(d[2]), "+f"(d[3])
                 : "r"(a[0]), "r"(a[1]), "r"(a[2]), "r"(a[3]), "r"(b0), "r"(b1));
}
__device__ __forceinline__ uint32_t packbf(__nv_bfloat16 a, __nv_bfloat16 b) {
    return (uint32_t)__bfloat16_as_ushort(a) | ((uint32_t)__bfloat16_as_ushort(b) << 16);
}

// ---------------- small kernels ----------------
__global__ void k_label(const int* __restrict__ raw) {
    __shared__ int is64;
    if (threadIdx.x == 0) {
        int all0 = 1;
        for (int i = 0; i < 64; i++) if (raw[2 * i + 1] != 0) { all0 = 0; break; }
        is64 = all0;
    }
    __syncthreads();
    int t = threadIdx.x;
    if (t < B_) g_label[t] = is64 ? raw[2 * t] : raw[t];
}

__global__ void k_xnorm(const float* __restrict__ x) {
    int b = blockIdx.x, t = threadIdx.x;
    float v = x[b * D_ + t];
    float s = v * v;
    #pragma unroll
    for (int o = 16; o > 0; o >>= 1) s += __shfl_down_sync(0xffffffffu, s, o);
    __shared__ float wpz[16];
    if ((t & 31) == 0) wpz[t >> 5] = s;
    __syncthreads();
    int h = t >> 6, k = t & 63;
    float ss = wpz[2 * h] + wpz[2 * h + 1];
    float xn = v * (1.0f / fmaxf(sqrtf(ss), 1e-12f));
    __nv_bfloat16 hi = __float2bfloat16(xn);
    __nv_bfloat16 lo = __float2bfloat16(xn - __bfloat162float(hi));
    unsigned by = (unsigned)b * 128u + 2u * (unsigned)k;
    unsigned sw = swz(by);
    g_Asw[h * 16384 + (sw >> 1)] = hi;
    g_Asw[h * 16384 + 8192 + (sw >> 1)] = lo;
}

// ---------------- pass1: GEMM + margin + quantize + partial sums ----------------
__global__ __launch_bounds__(256, 2) void k_pass1(const float* __restrict__ w) {
    extern __shared__ char sm[];
    const int tid = threadIdx.x, warp = tid >> 5, lane = tid & 31;
    const int h = blockIdx.y, tile = blockIdx.x, c0 = tile * TILE_C;
    uint32_t sb = smem_u32(sm);

    // copy A limbs (32KB, pre-swizzled; L2-resident after first wave)
    {
        const uint4* src = (const uint4*)(g_Asw + h * 16384);
        uint4* dst = (uint4*)(sm + OFF_AH);
        #pragma unroll
        for (int i = 0; i < 8; i++) dst[tid + 256 * i] = src[tid + 256 * i];
    }
    // convert B tile to bf16 limbs (+ per-column sq-norm partial)
    {
        int c = tid & 127, halfk = tid >> 7;
        int cg = c0 + c;
        bool valid = cg < C_;
        const float* wp0 = w + ((size_t)(h * DK + halfk * 32)) * C_ + cg;
        float ss = 0.f;
        #pragma unroll
        for (int i = 0; i < 16; i++) {
            float v0 = valid ? __ldg(wp0 + (size_t)(2 * i) * C_) : 0.f;
            float v1 = valid ? __ldg(wp0 + (size_t)(2 * i + 1) * C_) : 0.f;
            ss = fmaf(v0, v0, ss); ss = fmaf(v1, v1, ss);
            __nv_bfloat16 h0 = __float2bfloat16(v0);
            __nv_bfloat16 h1 = __float2bfloat16(v1);
            __nv_bfloat16 l0 = __float2bfloat16(v0 - __bfloat162float(h0));
            __nv_bfloat16 l1 = __float2bfloat16(v1 - __bfloat162float(h1));
            unsigned by = (unsigned)c * 128u + (unsigned)(halfk * 64 + 4 * i);
            unsigned sw = swz(by);
            *(uint32_t*)(sm + OFF_BH + sw) = packbf(h0, h1);
            *(uint32_t*)(sm + OFF_BL + sw) = packbf(l0, l1);
        }
        ((float*)(sm + OFF_WP))[c * 2 + halfk] = ss;
    }
    __syncthreads();
    if (tid < 128) {
        float* wp = (float*)(sm + OFF_WP);
        ((float*)(sm + OFF_WINV))[tid] =
            1.0f / fmaxf(sqrtf(wp[tid * 2] + wp[tid * 2 + 1]), 1e-12f);
    }

    const int wm = warp >> 1, wn = warp & 1;
    const int m0 = wm * 32, n0 = wn * 64;
    const int lrow = lane & 7, lt = lane >> 3;
    const int rowAo = lrow + (lt & 1) * 8;
    const int kbAo = (lt >> 1) * 16;
    const int rowBo = lrow + (lt >> 1) * 8;
    const int kbBo = (lt & 1) * 16;

    float acc[64];
    #pragma unroll
    for (int i = 0; i < 64; i++) acc[i] = 0.f;

    #pragma unroll
    for (int ks = 0; ks < 4; ks++) {
        uint32_t aH[2][4], aL[2][4];
        #pragma unroll
        for (int mb = 0; mb < 2; mb++) {
            unsigned sw = swz((unsigned)((m0 + mb * 16 + rowAo) * 128 + ks * 32 + kbAo));
            ldsm4(aH[mb], sb + OFF_AH + sw);
            ldsm4(aL[mb], sb + OFF_AL + sw);
        }
        #pragma unroll
        for (int p = 0; p < 4; p++) {
            unsigned sw = swz((unsigned)((n0 + p * 16 + rowBo) * 128 + ks * 32 + kbBo));
            uint32_t bH[4], bL[4];
            ldsm4(bH, sb + OFF_BH + sw);
            ldsm4(bL, sb + OFF_BL + sw);
            #pragma unroll
            for (int mb = 0; mb < 2; mb++) {
                float* d0 = acc + (mb * 8 + p * 2) * 4;
                float* d1 = acc + (mb * 8 + p * 2 + 1) * 4;
                mma_bf16(d0, aH[mb], bH[0], bH[1]);
                mma_bf16(d1, aH[mb], bH[2], bH[3]);
                mma_bf16(d0, aH[mb], bL[0], bL[1]);
                mma_bf16(d1, aH[mb], bL[2], bL[3]);
                mma_bf16(d0, aL[mb], bH[0], bH[1]);
                mma_bf16(d1, aL[mb], bH[2], bH[3]);
            }
        }
    }
    __syncthreads();

    // epilogue: cosine -> margin -> quantize int16 -> exp (for sums)
    const float* winv = (const float*)(sm + OFF_WINV);
    float* ps = (float*)(sm + OFF_PS);
    const int r0 = m0 + (lane >> 2);
    int labr[4];
    #pragma unroll
    for (int i = 0; i < 4; i++) labr[i] = g_label[r0 + (i >> 1) * 16 + (i & 1) * 8];

    float rsum[4] = {0.f, 0.f, 0.f, 0.f};
    const size_t wbase = (((size_t)h * NTILE + tile) * 8 + warp) * 1024;

    #pragma unroll
    for (int mb = 0; mb < 2; mb++) {
        #pragma unroll
        for (int pn = 0; pn < 8; pn++) {
            int cb = n0 + pn * 8 + (lane & 3) * 2;
            float w0 = winv[cb], w1 = winv[cb + 1];
            int cg = c0 + cb;
            #pragma unroll
            for (int pr = 0; pr < 2; pr++) {
                int row = r0 + mb * 16 + pr * 8;
                int lb = labr[mb * 2 + pr];
                float v0 = acc[(mb * 8 + pn) * 4 + pr * 2 + 0];
                float v1 = acc[(mb * 8 + pn) * 4 + pr * 2 + 1];
                float cos0 = v0 * w0, cos1 = v1 * w1;
                float q0 = 0.f, q1 = 0.f;
                if (cg < C_) {
                    float val = cos0;
                    if (cg == lb) {
                        float sn = sqrtf(fmaxf(1.f - cos0 * cos0, 0.f));
                        float ph = cos0 * COS_M - sn * SIN_M;
                        val = (cos0 > TH_) ? ph : (cos0 - MM_);
                        g_coslab[row * H_ + h] = cos0;
                    }
                    q0 = rintf(val * QS);
                    rsum[mb * 2 + pr] += __expf(fmaf(q0, QINV, -S_));
                }
                if (cg + 1 < C_) {
                    float val = cos1;
                    if (cg + 1 == lb) {
                        float sn = sqrtf(fmaxf(1.f - cos1 * cos1, 0.f));
                        float ph = cos1 * COS_M - sn * SIN_M;
                        val = (cos1 > TH_) ? ph : (cos1 - MM_);
                        g_coslab[row * H_ + h] = cos1;
                    }
                    q1 = rintf(val * QS);
                    rsum[mb * 2 + pr] += __expf(fmaf(q1, QINV, -S_));
                }
                uint32_t pk = ((uint32_t)(uint16_t)(short)__float2int_rn(q0)) |
                              (((uint32_t)(uint16_t)(short)__float2int_rn(q1)) << 16);
                g_Q[wbase + (size_t)(mb * 8 + pn) * 64 + pr * 32 + lane] = pk;
            }
        }
    }
    #pragma unroll
    for (int i = 0; i < 4; i++) {
        float v = rsum[i];
        v += __shfl_down_sync(0xffffffffu, v, 1);
        v += __shfl_down_sync(0xffffffffu, v, 2);
        if ((lane & 3) == 0)
            ps[(r0 + (i >> 1) * 16 + (i & 1) * 8) * 2 + wn] = v;
    }
    __syncthreads();
    if (tid < 128)
        g_psum[((size_t)h * NTILE + tile) * B_ + tid] = ps[tid * 2] + ps[tid * 2 + 1];
}

// ---------------- stage-1 reduction: 64 blocks ----------------
__global__ void k_sumexp1() {
    int h = blockIdx.x, ch = blockIdx.y, b = threadIdx.x;
    int t0 = ch * CHTILES;
    int t1 = min(t0 + CHTILES, NTILE);
    float s = 0.f;
    for (int t = t0; t < t1; t++) s += g_psum[((size_t)h * NTILE + t) * B_ + b];
    g_psum2[(h * NCHUNK + ch) * B_ + b] = s;
}

// ---------------- stage-2 + loss + invsum ----------------
__global__ void k_loss(float* __restrict__ out, int write_loss) {
    int tid = threadIdx.x;
    int b = tid >> 3, h = tid & 7;
    float s = 0.f;
    #pragma unroll
    for (int ch = 0; ch < NCHUNK; ch++) s += g_psum2[(h * NCHUNK + ch) * B_ + b];
    g_invsum[b * H_ + h] = 1.0f / s;

    float cos = g_coslab[b * H_ + h];
    float sine = sqrtf(fmaxf(1.0f - cos * cos, 0.0f));
    float phi = cos * COS_M - sine * SIN_M;
    float val = (cos > TH_) ? phi : (cos - MM_);
    float nll = -(S_ * val - S_ - logf(s));
    __shared__ float red[1024];
    red[tid] = nll;
    __syncthreads();
    #pragma unroll
    for (int st = 512; st > 0; st >>= 1) {
        if (tid < st) red[tid] += red[tid + st];
        __syncthreads();
    }
    if (tid == 0 && write_loss) out[(size_t)B_ * C_] = red[0] * (1.0f / (B_ * H_));
}

// ---------------- k_out: head-mean of softmax from quantized logits --------
__global__ __launch_bounds__(256, 2) void k_out(float* __restrict__ out) {
    extern __shared__ char sm[];
    const int tid = threadIdx.x, warp = tid >> 5, lane = tid & 31;
    const int tile = blockIdx.x, c0 = tile * TILE_C;
    float* invs = (float*)(sm + KO_INV);
    float* stg = (float*)(sm + KO_STG);
    #pragma unroll
    for (int i = 0; i < 4; i++) invs[tid + 256 * i] = g_invsum[tid + 256 * i] * 0.125f;
    __syncthreads();

    const int wm = warp >> 1, wn = warp & 1;
    const int m0 = wm * 32, n0 = wn * 64;
    const int r0 = m0 + (lane >> 2);

    float acc[64];
    #pragma unroll
    for (int i = 0; i < 64; i++) acc[i] = 0.f;

    for (int h = 0; h < H_; h++) {
        const uint32_t* Qp = g_Q + (((size_t)h * NTILE + tile) * 8 + warp) * 1024;
        float s[4];
        #pragma unroll
        for (int i = 0; i < 4; i++)
            s[i] = invs[(r0 + (i >> 1) * 16 + (i & 1) * 8) * H_ + h];
        #pragma unroll
        for (int mb = 0; mb < 2; mb++)
            #pragma unroll
            for (int pn = 0; pn < 8; pn++)
                #pragma unroll
                for (int pr = 0; pr < 2; pr++) {
                    uint32_t pk = Qp[(size_t)(mb * 8 + pn) * 64 + pr * 32 + lane];
                    float q0 = (float)(short)(pk & 0xFFFFu);
                    float q1 = (float)(short)(pk >> 16);
                    float sv = s[mb * 2 + pr];
                    float e0 = __expf(fmaf(q0, QINV, -S_));
                    float e1 = __expf(fmaf(q1, QINV, -S_));
                    int ai = (mb * 8 + pn) * 4 + pr * 2;
                    acc[ai]     = fmaf(e0, sv, acc[ai]);
                    acc[ai + 1] = fmaf(e1, sv, acc[ai + 1]);
                }
    }
    #pragma unroll
    for (int mb = 0; mb < 2; mb++)
        #pragma unroll
        for (int pn = 0; pn < 8; pn++)
            #pragma unroll
            for (int pr = 0; pr < 2; pr++) {
                int row = r0 + mb * 16 + pr * 8;
                int col = n0 + pn * 8 + (lane & 3) * 2;
                int ai = (mb * 8 + pn) * 4 + pr * 2;
                stg[row * 130 + col] = acc[ai];
                stg[row * 130 + col + 1] = acc[ai + 1];
            }
    __syncthreads();
    for (int idx = tid; idx < 4096; idx += 256) {
        int b = idx >> 5, c4 = (idx & 31) << 2;
        int cg = c0 + c4;
        if (cg + 3 < C_) {
            float4 vv = make_float4(stg[b * 130 + c4], stg[b * 130 + c4 + 1],
                                    stg[b * 130 + c4 + 2], stg[b * 130 + c4 + 3]);
            *(float4*)&out[(size_t)b * C_ + cg] = vv;
        } else {
            #pragma unroll
            for (int j = 0; j < 4; j++)
                if (cg + j < C_) out[(size_t)b * C_ + cg + j] = stg[b * 130 + c4 + j];
        }
    }
}

// ---------------- launcher ----------------
extern "C" void kernel_launch(void* const* d_in, const int* in_sizes, int n_in,
                              void* d_out, int out_size) {
    const float* x = (const float*)d_in[0];
    const float* w = (const float*)d_in[1];
    const int*   lab = (const int*)d_in[2];
    float* out = (float*)d_out;
    (void)in_sizes; (void)n_in;

    static int inited = 0;
    if (!inited) {
        cudaFuncSetAttribute(k_pass1, cudaFuncAttributeMaxDynamicSharedMemorySize, SMEM1);
        cudaFuncSetAttribute(k_out, cudaFuncAttributeMaxDynamicSharedMemorySize, SMEM2);
        inited = 1;
    }
    int write_loss = (out_size > B_ * C_) ? 1 : 0;

    k_label<<<1, 128>>>(lab);
    k_xnorm<<<B_, D_>>>(x);
    {
        dim3 g1(NTILE, H_);
        k_pass1<<<g1, 256, SMEM1>>>(w);
    }
    {
        dim3 g2(H_, NCHUNK);
        k_sumexp1<<<g2, B_>>>();
    }
    k_loss<<<1, 1024>>>(out, write_loss);
    k_out<<<NTILE, 256, SMEM2>>>(out);
}

// round 5
// speedup vs baseline: 2.7332x; 1.1200x over previous
#include <cuda_runtime.h>
#include <cuda_bf16.h>
#include <math.h>
#include <stdint.h>
#include <stddef.h>

#define B_ 128
#define H_ 8
#define DK 64
#define C_ 50000
#define D_ 512
#define TILE_C 64
#define NTILE 782          // 782*64 = 50048 >= 50000
#define NCHUNK 32
#define CHTILES 25         // 32*25 = 800 >= 782

#define COS_M 0.9800665778412416f
#define SIN_M 0.19866933079506122f
#define TH_  (-0.9800665778412416f)
#define MM_  0.039733866159012244f
#define S_   30.0f
#define QS   31500.0f
#define QINV (S_ / QS)

// ---- pass1 smem layout (bytes) ----
#define OFF_AH 0
#define OFF_AL 16384
#define OFF_BH 32768
#define OFF_BL 40960
#define OFF_WINV 49152     // 64 floats
#define OFF_WP   49408     // 256 floats
#define OFF_PS   50432     // 256 floats
#define SMEM1    51456

// ---- k_out smem ----
#define KO_INV 0
#define KO_STG 4096
#define SMEM2 (4096 + 128 * 68 * 4)   // 38912

// ---------------- device scratch ----------------
__device__ __align__(16) __nv_bfloat16 g_Asw[H_ * 16384];   // per head: [hi][lo], swizzled
__device__ uint32_t g_Q[(size_t)H_ * NTILE * 8 * 512];      // packed int16 q-pairs (102MB)
__device__ float g_psum[H_ * NTILE * B_];
__device__ float g_psum2[H_ * NCHUNK * B_];
__device__ float g_invsum[B_ * H_];
__device__ float g_coslab[B_ * H_];
__device__ int   g_label[B_];

// ---------------- helpers ----------------
__device__ __forceinline__ uint32_t smem_u32(const void* p) {
    uint32_t a;
    asm("{ .reg .u64 t; cvta.to.shared.u64 t, %1; cvt.u32.u64 %0, t; }" : "=r"(a) : "l"(p));
    return a;
}
__device__ __forceinline__ unsigned swz(unsigned by) { return by ^ ((by >> 3) & 0x70); }

__device__ __forceinline__ void ldsm4(uint32_t* r, uint32_t addr) {
    asm volatile("ldmatrix.sync.aligned.m8n8.x4.shared.b16 {%0,%1,%2,%3}, [%4];"
                 : "=r"(r[0]), "=r"(r[1]), "=r"(r[2]), "=r"(r[3]) : "r"(addr));
}
__device__ __forceinline__ void mma_bf16(float* d, const uint32_t* a, uint32_t b0, uint32_t b1) {
    asm volatile("mma.sync.aligned.m16n8k16.row.col.f32.bf16.bf16.f32 "
                 "{%0,%1,%2,%3}, {%4,%5,%6,%7}, {%8,%9}, {%0,%1,%2,%3};"
                 : "+f"(d[0]), "+f"(d[1]), "+f"(d[2]), "+f"(d[3])
                 : "r"(a[0]), "r"(a[1]), "r"(a[2]), "r"(a[3]), "r"(b0), "r"(b1));
}
__device__ __forceinline__ uint32_t packbf(__nv_bfloat16 a, __nv_bfloat16 b) {
    return (uint32_t)__bfloat16_as_ushort(a) | ((uint32_t)__bfloat16_as_ushort(b) << 16);
}

// ---------------- small kernels ----------------
__global__ void k_label(const int* __restrict__ raw) {
    __shared__ int is64;
    if (threadIdx.x == 0) {
        int all0 = 1;
        for (int i = 0; i < 64; i++) if (raw[2 * i + 1] != 0) { all0 = 0; break; }
        is64 = all0;
    }
    __syncthreads();
    int t = threadIdx.x;
    if (t < B_) g_label[t] = is64 ? raw[2 * t] : raw[t];
}

__global__ void k_xnorm(const float* __restrict__ x) {
    int b = blockIdx.x, t = threadIdx.x;
    float v = x[b * D_ + t];
    float s = v * v;
    #pragma unroll
    for (int o = 16; o > 0; o >>= 1) s += __shfl_down_sync(0xffffffffu, s, o);
    __shared__ float wpz[16];
    if ((t & 31) == 0) wpz[t >> 5] = s;
    __syncthreads();
    int h = t >> 6, k = t & 63;
    float ss = wpz[2 * h] + wpz[2 * h + 1];
    float xn = v * (1.0f / fmaxf(sqrtf(ss), 1e-12f));
    __nv_bfloat16 hi = __float2bfloat16(xn);
    __nv_bfloat16 lo = __float2bfloat16(xn - __bfloat162float(hi));
    unsigned by = (unsigned)b * 128u + 2u * (unsigned)k;
    unsigned sw = swz(by);
    g_Asw[h * 16384 + (sw >> 1)] = hi;
    g_Asw[h * 16384 + 8192 + (sw >> 1)] = lo;
}

// ---------------- pass1: GEMM + margin + quantize + partial sums ----------------
__global__ __launch_bounds__(256, 3) void k_pass1(const float* __restrict__ w) {
    extern __shared__ char sm[];
    const int tid = threadIdx.x, warp = tid >> 5, lane = tid & 31;
    const int h = blockIdx.y, tile = blockIdx.x, c0 = tile * TILE_C;
    uint32_t sb = smem_u32(sm);

    // copy A limbs (32KB, pre-swizzled; L2-resident)
    {
        const uint4* src = (const uint4*)(g_Asw + h * 16384);
        uint4* dst = (uint4*)(sm + OFF_AH);
        #pragma unroll
        for (int i = 0; i < 8; i++) dst[tid + 256 * i] = src[tid + 256 * i];
    }
    // convert B tile (64 cols) to bf16 limbs (+ per-column sq-norm partial)
    {
        int c = tid & 63, kg = tid >> 6;          // 64 cols x 4 k-groups of 16
        int cg = c0 + c;
        bool valid = cg < C_;
        const float* wp0 = w + ((size_t)(h * DK + kg * 16)) * C_ + cg;
        float ss = 0.f;
        #pragma unroll
        for (int i = 0; i < 8; i++) {
            float v0 = valid ? __ldg(wp0 + (size_t)(2 * i) * C_) : 0.f;
            float v1 = valid ? __ldg(wp0 + (size_t)(2 * i + 1) * C_) : 0.f;
            ss = fmaf(v0, v0, ss); ss = fmaf(v1, v1, ss);
            __nv_bfloat16 h0 = __float2bfloat16(v0);
            __nv_bfloat16 h1 = __float2bfloat16(v1);
            __nv_bfloat16 l0 = __float2bfloat16(v0 - __bfloat162float(h0));
            __nv_bfloat16 l1 = __float2bfloat16(v1 - __bfloat162float(h1));
            unsigned by = (unsigned)c * 128u + (unsigned)(kg * 32 + 4 * i);
            unsigned sw = swz(by);
            *(uint32_t*)(sm + OFF_BH + sw) = packbf(h0, h1);
            *(uint32_t*)(sm + OFF_BL + sw) = packbf(l0, l1);
        }
        ((float*)(sm + OFF_WP))[c * 4 + kg] = ss;
    }
    __syncthreads();
    if (tid < 64) {
        float* wp = (float*)(sm + OFF_WP);
        ((float*)(sm + OFF_WINV))[tid] =
            1.0f / fmaxf(sqrtf(wp[tid * 4] + wp[tid * 4 + 1] + wp[tid * 4 + 2] + wp[tid * 4 + 3]),
                         1e-12f);
    }

    const int wm = warp >> 1, wn = warp & 1;
    const int m0 = wm * 32, n0 = wn * 32;
    const int lrow = lane & 7, lt = lane >> 3;
    const int rowAo = lrow + (lt & 1) * 8;
    const int kbAo = (lt >> 1) * 16;
    const int rowBo = lrow + (lt >> 1) * 8;
    const int kbBo = (lt & 1) * 16;

    float acc[32];
    #pragma unroll
    for (int i = 0; i < 32; i++) acc[i] = 0.f;

    #pragma unroll
    for (int ks = 0; ks < 4; ks++) {
        uint32_t aH[2][4], aL[2][4];
        #pragma unroll
        for (int mb = 0; mb < 2; mb++) {
            unsigned sw = swz((unsigned)((m0 + mb * 16 + rowAo) * 128 + ks * 32 + kbAo));
            ldsm4(aH[mb], sb + OFF_AH + sw);
            ldsm4(aL[mb], sb + OFF_AL + sw);
        }
        #pragma unroll
        for (int p = 0; p < 2; p++) {
            unsigned sw = swz((unsigned)((n0 + p * 16 + rowBo) * 128 + ks * 32 + kbBo));
            uint32_t bH[4], bL[4];
            ldsm4(bH, sb + OFF_BH + sw);
            ldsm4(bL, sb + OFF_BL + sw);
            #pragma unroll
            for (int mb = 0; mb < 2; mb++) {
                float* d0 = acc + (mb * 4 + p * 2) * 4;
                float* d1 = acc + (mb * 4 + p * 2 + 1) * 4;
                mma_bf16(d0, aH[mb], bH[0], bH[1]);
                mma_bf16(d1, aH[mb], bH[2], bH[3]);
                mma_bf16(d0, aH[mb], bL[0], bL[1]);
                mma_bf16(d1, aH[mb], bL[2], bL[3]);
                mma_bf16(d0, aL[mb], bH[0], bH[1]);
                mma_bf16(d1, aL[mb], bH[2], bH[3]);
            }
        }
    }
    __syncthreads();

    // epilogue: cosine -> margin -> quantize int16 -> exp (for sums)
    const float* winv = (const float*)(sm + OFF_WINV);
    float* ps = (float*)(sm + OFF_PS);
    const int r0 = m0 + (lane >> 2);
    int labr[4];
    #pragma unroll
    for (int i = 0; i < 4; i++) labr[i] = g_label[r0 + (i >> 1) * 16 + (i & 1) * 8];

    float rsum[4] = {0.f, 0.f, 0.f, 0.f};
    const size_t wbase = (((size_t)h * NTILE + tile) * 8 + warp) * 512;

    #pragma unroll
    for (int mb = 0; mb < 2; mb++) {
        #pragma unroll
        for (int pn = 0; pn < 4; pn++) {
            int cb = n0 + pn * 8 + (lane & 3) * 2;
            float w0 = winv[cb], w1 = winv[cb + 1];
            int cg = c0 + cb;
            uint2 pk2;
            #pragma unroll
            for (int pr = 0; pr < 2; pr++) {
                int row = r0 + mb * 16 + pr * 8;
                int lb = labr[mb * 2 + pr];
                float v0 = acc[(mb * 4 + pn) * 4 + pr * 2 + 0];
                float v1 = acc[(mb * 4 + pn) * 4 + pr * 2 + 1];
                float cos0 = v0 * w0, cos1 = v1 * w1;
                float q0 = 0.f, q1 = 0.f;
                if (cg < C_) {
                    float val = cos0;
                    if (cg == lb) {
                        float sn = sqrtf(fmaxf(1.f - cos0 * cos0, 0.f));
                        float ph = cos0 * COS_M - sn * SIN_M;
                        val = (cos0 > TH_) ? ph : (cos0 - MM_);
                        g_coslab[row * H_ + h] = cos0;
                    }
                    q0 = rintf(val * QS);
                    rsum[mb * 2 + pr] += __expf(fmaf(q0, QINV, -S_));
                }
                if (cg + 1 < C_) {
                    float val = cos1;
                    if (cg + 1 == lb) {
                        float sn = sqrtf(fmaxf(1.f - cos1 * cos1, 0.f));
                        float ph = cos1 * COS_M - sn * SIN_M;
                        val = (cos1 > TH_) ? ph : (cos1 - MM_);
                        g_coslab[row * H_ + h] = cos1;
                    }
                    q1 = rintf(val * QS);
                    rsum[mb * 2 + pr] += __expf(fmaf(q1, QINV, -S_));
                }
                uint32_t pk = ((uint32_t)(uint16_t)(short)__float2int_rn(q0)) |
                              (((uint32_t)(uint16_t)(short)__float2int_rn(q1)) << 16);
                if (pr == 0) pk2.x = pk; else pk2.y = pk;
            }
            *(uint2*)&g_Q[wbase + (size_t)(mb * 4 + pn) * 64 + lane * 2] = pk2;
        }
    }
    #pragma unroll
    for (int i = 0; i < 4; i++) {
        float v = rsum[i];
        v += __shfl_down_sync(0xffffffffu, v, 1);
        v += __shfl_down_sync(0xffffffffu, v, 2);
        if ((lane & 3) == 0)
            ps[(r0 + (i >> 1) * 16 + (i & 1) * 8) * 2 + wn] = v;
    }
    __syncthreads();
    if (tid < 128)
        g_psum[((size_t)h * NTILE + tile) * B_ + tid] = ps[tid * 2] + ps[tid * 2 + 1];
}

// ---------------- stage-1 reduction: 256 blocks ----------------
__global__ void k_sumexp1() {
    int h = blockIdx.x, ch = blockIdx.y, b = threadIdx.x;
    int t0 = ch * CHTILES;
    int t1 = min(t0 + CHTILES, NTILE);
    float s = 0.f;
    for (int t = t0; t < t1; t++) s += g_psum[((size_t)h * NTILE + t) * B_ + b];
    g_psum2[(h * NCHUNK + ch) * B_ + b] = s;
}

// ---------------- stage-2 + loss + invsum ----------------
__global__ void k_loss(float* __restrict__ out, int write_loss) {
    int tid = threadIdx.x;
    int b = tid >> 3, h = tid & 7;
    float s = 0.f;
    #pragma unroll
    for (int ch = 0; ch < NCHUNK; ch++) s += g_psum2[(h * NCHUNK + ch) * B_ + b];
    g_invsum[b * H_ + h] = 1.0f / s;

    float cos = g_coslab[b * H_ + h];
    float sine = sqrtf(fmaxf(1.0f - cos * cos, 0.0f));
    float phi = cos * COS_M - sine * SIN_M;
    float val = (cos > TH_) ? phi : (cos - MM_);
    float nll = -(S_ * val - S_ - logf(s));
    __shared__ float red[1024];
    red[tid] = nll;
    __syncthreads();
    #pragma unroll
    for (int st = 512; st > 0; st >>= 1) {
        if (tid < st) red[tid] += red[tid + st];
        __syncthreads();
    }
    if (tid == 0 && write_loss) out[(size_t)B_ * C_] = red[0] * (1.0f / (B_ * H_));
}

// ---------------- k_out: head-mean of softmax from quantized logits --------
__global__ __launch_bounds__(256, 4) void k_out(float* __restrict__ out) {
    extern __shared__ char sm[];
    const int tid = threadIdx.x, warp = tid >> 5, lane = tid & 31;
    const int tile = blockIdx.x, c0 = tile * TILE_C;
    float* invs = (float*)(sm + KO_INV);
    float* stg = (float*)(sm + KO_STG);
    #pragma unroll
    for (int i = 0; i < 4; i++) invs[tid + 256 * i] = g_invsum[tid + 256 * i] * 0.125f;
    __syncthreads();

    const int wm = warp >> 1, wn = warp & 1;
    const int m0 = wm * 32, n0 = wn * 32;
    const int r0 = m0 + (lane >> 2);

    float acc[32];
    #pragma unroll
    for (int i = 0; i < 32; i++) acc[i] = 0.f;

    for (int h = 0; h < H_; h++) {
        const uint32_t* Qp = g_Q + (((size_t)h * NTILE + tile) * 8 + warp) * 512;
        float s[4];
        #pragma unroll
        for (int i = 0; i < 4; i++)
            s[i] = invs[(r0 + (i >> 1) * 16 + (i & 1) * 8) * H_ + h];
        #pragma unroll
        for (int mb = 0; mb < 2; mb++)
            #pragma unroll
            for (int pn = 0; pn < 4; pn++) {
                uint2 pk2 = *(const uint2*)&Qp[(size_t)(mb * 4 + pn) * 64 + lane * 2];
                #pragma unroll
                for (int pr = 0; pr < 2; pr++) {
                    uint32_t pk = pr ? pk2.y : pk2.x;
                    float q0 = (float)(short)(pk & 0xFFFFu);
                    float q1 = (float)(short)(pk >> 16);
                    float sv = s[mb * 2 + pr];
                    float e0 = __expf(fmaf(q0, QINV, -S_));
                    float e1 = __expf(fmaf(q1, QINV, -S_));
                    int ai = (mb * 4 + pn) * 4 + pr * 2;
                    acc[ai]     = fmaf(e0, sv, acc[ai]);
                    acc[ai + 1] = fmaf(e1, sv, acc[ai + 1]);
                }
            }
    }
    #pragma unroll
    for (int mb = 0; mb < 2; mb++)
        #pragma unroll
        for (int pn = 0; pn < 4; pn++)
            #pragma unroll
            for (int pr = 0; pr < 2; pr++) {
                int row = r0 + mb * 16 + pr * 8;
                int col = n0 + pn * 8 + (lane & 3) * 2;
                int ai = (mb * 4 + pn) * 4 + pr * 2;
                stg[row * 68 + col] = acc[ai];
                stg[row * 68 + col + 1] = acc[ai + 1];
            }
    __syncthreads();
    for (int idx = tid; idx < 2048; idx += 256) {
        int b = idx >> 4, c4 = (idx & 15) << 2;
        int cg = c0 + c4;
        if (cg + 3 < C_) {
            float4 vv = make_float4(stg[b * 68 + c4], stg[b * 68 + c4 + 1],
                                    stg[b * 68 + c4 + 2], stg[b * 68 + c4 + 3]);
            *(float4*)&out[(size_t)b * C_ + cg] = vv;
        } else {
            #pragma unroll
            for (int j = 0; j < 4; j++)
                if (cg + j < C_) out[(size_t)b * C_ + cg + j] = stg[b * 68 + c4 + j];
        }
    }
}

// ---------------- launcher ----------------
extern "C" void kernel_launch(void* const* d_in, const int* in_sizes, int n_in,
                              void* d_out, int out_size) {
    const float* x = (const float*)d_in[0];
    const float* w = (const float*)d_in[1];
    const int*   lab = (const int*)d_in[2];
    float* out = (float*)d_out;
    (void)in_sizes; (void)n_in;

    static int inited = 0;
    if (!inited) {
        cudaFuncSetAttribute(k_pass1, cudaFuncAttributeMaxDynamicSharedMemorySize, SMEM1);
        cudaFuncSetAttribute(k_out, cudaFuncAttributeMaxDynamicSharedMemorySize, SMEM2);
        inited = 1;
    }
    int write_loss = (out_size > B_ * C_) ? 1 : 0;

    k_label<<<1, 128>>>(lab);
    k_xnorm<<<B_, D_>>>(x);
    {
        dim3 g1(NTILE, H_);
        k_pass1<<<g1, 256, SMEM1>>>(w);
    }
    {
        dim3 g2(H_, NCHUNK);
        k_sumexp1<<<g2, B_>>>();
    }
    k_loss<<<1, 1024>>>(out, write_loss);
    k_out<<<NTILE, 256, SMEM2>>>(out);
}